// round 2
// baseline (speedup 1.0000x reference)
#include <cuda_runtime.h>
#include <math.h>

// ---------------- problem constants ----------------
#define NF      32          // B*S frames
#define C       64
#define H       96
#define W       96
#define FEAT    2304        // C*6*6
#define DIM     768
#define M_TOK   (NF*256)                    // 8192
#define TOK_ELEMS   (M_TOK*DIM)             // 6291456
#define FRAME_STRIDE (C*H*W)

// ---------------- packed f32x2 helpers ----------------
__device__ __forceinline__ unsigned long long pack2f(float lo, float hi){
    unsigned long long r;
    asm("mov.b64 %0, {%1, %2};" : "=l"(r)
        : "r"(__float_as_uint(lo)), "r"(__float_as_uint(hi)));
    return r;
}
__device__ __forceinline__ unsigned long long fma2(unsigned long long a,
                                                   unsigned long long b,
                                                   unsigned long long c){
    unsigned long long d;
    asm("fma.rn.f32x2 %0, %1, %2, %3;" : "=l"(d) : "l"(a), "l"(b), "l"(c));
    return d;
}
__device__ __forceinline__ float2 unpack2f(unsigned long long v){
    unsigned lo, hi;
    asm("mov.b64 {%0, %1}, %2;" : "=r"(lo), "=r"(hi) : "l"(v));
    return make_float2(__uint_as_float(lo), __uint_as_float(hi));
}

__device__ __forceinline__ float gelu_exact(float x){
    return 0.5f*x*(1.0f + erff(x*0.7071067811865476f));
}

// =====================================================================
// Kernel 1: 3x3 conv (pad 1) + bias + BN + exact GELU + patch/mask
// writes masked patches directly into d_out (no intermediate buffer).
// Block: 256 threads, tile 32(x) x 8(y) spatial, 16 c_out.
// Thread: 4 c_out x 4 px; inner loop uses fma.rn.f32x2 (packed pairs).
// Double-buffered smem staging: 1 barrier per c_in.
// =====================================================================
__global__ __launch_bounds__(256, 2) void conv_bn_gelu_patch_kernel(
    const float* __restrict__ x,
    const float* __restrict__ cw,
    const float* __restrict__ cb,
    const float* __restrict__ gamma,
    const float* __restrict__ beta,
    const float* __restrict__ mean,
    const float* __restrict__ var,
    const float* __restrict__ mask,
    float* __restrict__ out_patches)
{
    __shared__ float s_in[2][10][36];                 // halo tile, double buffered
    __shared__ unsigned long long s_w2[2][16][9];     // broadcast weight pairs {w,w}
    __shared__ float s_mask[36];

    const int tid = threadIdx.x;
    const int tc  = tid & 3;         // c_out sub-group (4 c_out each)
    const int tx  = (tid >> 2) & 7;  // x sub-tile (4 px each)
    const int ty  = tid >> 5;        // y row (0..7)

    const int bx    = blockIdx.x;        // 0..2
    const int by    = blockIdx.y;        // 0..11
    const int frame = blockIdx.z >> 2;   // 0..31
    const int cog   = blockIdx.z & 3;    // c_out group of 16

    const float* xin = x + (long)frame * FRAME_STRIDE;
    const int y  = by*8 + ty;
    const int x0 = bx*32 + tx*4;

    // ---- prologue staging (ci = 0) ----
    if (tid < 36) s_mask[tid] = mask[tid];
    for (int i = tid; i < 340; i += 256){
        int r = i/34, cc = i%34;
        int gy = by*8 + r - 1, gx = bx*32 + cc - 1;
        float v = 0.f;
        if (gy>=0 && gy<H && gx>=0 && gx<W) v = xin[gy*W + gx];
        s_in[0][r][cc] = v;
    }
    if (tid < 144){
        int col = tid/9, k = tid%9;
        float w = cw[((cog*16+col)*C)*9 + k];
        s_w2[0][col][k] = pack2f(w, w);
    }
    __syncthreads();

    unsigned long long acc2[4][2];
    #pragma unroll
    for (int q=0;q<4;q++){ acc2[q][0]=0ULL; acc2[q][1]=0ULL; }

    for (int ci = 0; ci < C; ci++){
        const int cur = ci & 1;
        // ---- issue loads for next channel (hidden behind compute) ----
        float vin0 = 0.f, vin1 = 0.f, wld = 0.f;
        const bool hasnext = (ci + 1 < C);
        if (hasnext){
            const float* xc = xin + (long)(ci+1)*H*W;
            { int r = tid/34, cc = tid%34;
              int gy = by*8 + r - 1, gx = bx*32 + cc - 1;
              if (gy>=0 && gy<H && gx>=0 && gx<W) vin0 = xc[gy*W + gx]; }
            if (tid + 256 < 340){
              int i1 = tid + 256;
              int r = i1/34, cc = i1%34;
              int gy = by*8 + r - 1, gx = bx*32 + cc - 1;
              if (gy>=0 && gy<H && gx>=0 && gx<W) vin1 = xc[gy*W + gx]; }
            if (tid < 144){
              int col = tid/9, k = tid%9;
              wld = cw[((cog*16+col)*C + ci + 1)*9 + k]; }
        }

        // ---- compute on current buffer ----
        unsigned long long p[3][5];
        #pragma unroll
        for (int dy=0; dy<3; dy++){
            const float* rp = &s_in[cur][ty+dy][tx*4];
            float4 v4 = *(const float4*)rp;
            float2 v2 = *(const float2*)(rp + 4);
            p[dy][0] = pack2f(v4.x, v4.y);
            p[dy][1] = pack2f(v4.y, v4.z);
            p[dy][2] = pack2f(v4.z, v4.w);
            p[dy][3] = pack2f(v4.w, v2.x);
            p[dy][4] = pack2f(v2.x, v2.y);
        }
        #pragma unroll
        for (int q=0;q<4;q++){
            #pragma unroll
            for (int ky=0;ky<3;ky++){
                #pragma unroll
                for (int kx=0;kx<3;kx++){
                    unsigned long long w = s_w2[cur][tc*4+q][ky*3+kx];
                    acc2[q][0] = fma2(p[ky][kx],   w, acc2[q][0]);
                    acc2[q][1] = fma2(p[ky][kx+2], w, acc2[q][1]);
                }
            }
        }

        // ---- commit staged data to other buffer ----
        if (hasnext){
            const int nxt = cur ^ 1;
            { int r = tid/34, cc = tid%34; s_in[nxt][r][cc] = vin0; }
            if (tid + 256 < 340){
                int i1 = tid + 256;
                int r = i1/34, cc = i1%34; s_in[nxt][r][cc] = vin1; }
            if (tid < 144){
                int col = tid/9, k = tid%9;
                s_w2[nxt][col][k] = pack2f(wld, wld); }
        }
        __syncthreads();
    }

    // ---- epilogue: bias + BN + GELU + mask, scatter into patches layout ----
    const int l = y / 6, i_in = y - l*6;
    #pragma unroll
    for (int q=0;q<4;q++){
        const int co = cog*16 + tc*4 + q;
        const float s  = gamma[co] * rsqrtf(var[co] + 1e-5f);
        const float sh = beta[co] - mean[co]*s;
        const float b  = cb[co];
        float2 lo = unpack2f(acc2[q][0]);
        float2 hi = unpack2f(acc2[q][1]);
        float v[4] = {lo.x, lo.y, hi.x, hi.y};
        #pragma unroll
        for (int px=0;px<4;px++){
            const int xg = x0 + px;
            const int r  = xg / 6, j = xg - r*6;
            float o = gelu_exact((v[px] + b)*s + sh) * s_mask[i_in*6 + j];
            out_patches[((((long)frame*256 + l*16 + r)*64 + co)*36) + i_in*6 + j] = o;
        }
    }
}

// =====================================================================
// Kernel 2: tokens = gelu(A @ Wp^T + bias)
// A = masked patches [8192, 2304], Wp [768, 2304], both K-major.
// 64x64 tile, BK=32, double-buffered smem, fma.rn.f32x2 microtile
// (4 m x 2 n-pairs per thread).
// =====================================================================
__global__ __launch_bounds__(256, 3) void gemm_tokens_kernel(
    const float* __restrict__ A,
    const float* __restrict__ Wp,
    const float* __restrict__ bias,
    float* __restrict__ tok)
{
    __shared__ float s_a[2][32][68];   // [k][m]
    __shared__ float s_b[2][32][68];   // [k][n]

    const int tid = threadIdx.x;
    const int bn  = blockIdx.x;     // 0..11
    const int bm  = blockIdx.y;     // 0..127
    const int txx = tid & 15;       // n micro (4 n = 2 pairs)
    const int tyy = tid >> 4;       // m micro (4 m)

    unsigned long long acc2[4][2];
    #pragma unroll
    for (int im=0;im<4;im++){ acc2[im][0]=0ULL; acc2[im][1]=0ULL; }

    const int rowA = bm*64 + (tid >> 3);          // staging row ids (h=0)
    const int kkS  = (tid & 7) << 2;

    // ---- prologue: stage kt=0 ----
    #pragma unroll
    for (int h=0; h<2; h++){
        int li  = tid + h*256;
        int row = li >> 3;
        int kk  = (li & 7) << 2;
        float4 av = *(const float4*)(A  + (long)(bm*64+row)*FEAT + kk);
        float4 bv = *(const float4*)(Wp + (long)(bn*64+row)*FEAT + kk);
        s_a[0][kk+0][row]=av.x; s_a[0][kk+1][row]=av.y;
        s_a[0][kk+2][row]=av.z; s_a[0][kk+3][row]=av.w;
        s_b[0][kk+0][row]=bv.x; s_b[0][kk+1][row]=bv.y;
        s_b[0][kk+2][row]=bv.z; s_b[0][kk+3][row]=bv.w;
    }
    __syncthreads();

    const int NKT = FEAT/32;   // 72
    for (int kti = 0; kti < NKT; kti++){
        const int cur = kti & 1;
        const bool hasnext = (kti + 1 < NKT);
        float4 av[2], bv[2];
        if (hasnext){
            const int kt = (kti+1)*32;
            #pragma unroll
            for (int h=0; h<2; h++){
                int li  = tid + h*256;
                int row = li >> 3;
                int kk  = (li & 7) << 2;
                av[h] = *(const float4*)(A  + (long)(bm*64+row)*FEAT + kt + kk);
                bv[h] = *(const float4*)(Wp + (long)(bn*64+row)*FEAT + kt + kk);
            }
        }

        #pragma unroll
        for (int k=0;k<32;k++){
            float4 a4 = *(const float4*)&s_a[cur][k][tyy*4];
            ulonglong2 b2 = *(const ulonglong2*)&s_b[cur][k][txx*4];
            unsigned long long am[4];
            am[0]=pack2f(a4.x,a4.x); am[1]=pack2f(a4.y,a4.y);
            am[2]=pack2f(a4.z,a4.z); am[3]=pack2f(a4.w,a4.w);
            #pragma unroll
            for (int im=0;im<4;im++){
                acc2[im][0] = fma2(am[im], b2.x, acc2[im][0]);
                acc2[im][1] = fma2(am[im], b2.y, acc2[im][1]);
            }
        }

        if (hasnext){
            const int nxt = cur ^ 1;
            #pragma unroll
            for (int h=0; h<2; h++){
                int li  = tid + h*256;
                int row = li >> 3;
                int kk  = (li & 7) << 2;
                s_a[nxt][kk+0][row]=av[h].x; s_a[nxt][kk+1][row]=av[h].y;
                s_a[nxt][kk+2][row]=av[h].z; s_a[nxt][kk+3][row]=av[h].w;
                s_b[nxt][kk+0][row]=bv[h].x; s_b[nxt][kk+1][row]=bv[h].y;
                s_b[nxt][kk+2][row]=bv[h].z; s_b[nxt][kk+3][row]=bv[h].w;
            }
        }
        __syncthreads();
    }

    // ---- epilogue: bias + gelu, vectorized stores ----
    const int n0 = bn*64 + txx*4;
    float4 b4 = *(const float4*)(bias + n0);
    #pragma unroll
    for (int im=0;im<4;im++){
        const int m = bm*64 + tyy*4 + im;
        float2 v0 = unpack2f(acc2[im][0]);
        float2 v1 = unpack2f(acc2[im][1]);
        float4 o;
        o.x = gelu_exact(v0.x + b4.x);
        o.y = gelu_exact(v0.y + b4.y);
        o.z = gelu_exact(v1.x + b4.z);
        o.w = gelu_exact(v1.y + b4.w);
        *(float4*)(tok + (long)m*DIM + n0) = o;
    }
}

// =====================================================================
extern "C" void kernel_launch(void* const* d_in, const int* in_sizes, int n_in,
                              void* d_out, int out_size)
{
    const float* x      = (const float*)d_in[0];
    const float* conv_w = (const float*)d_in[1];
    const float* conv_b = (const float*)d_in[2];
    const float* gamma  = (const float*)d_in[3];
    const float* beta   = (const float*)d_in[4];
    const float* mean   = (const float*)d_in[5];
    const float* var    = (const float*)d_in[6];
    const float* proj_w = (const float*)d_in[7];
    const float* proj_b = (const float*)d_in[8];
    const float* mask   = (const float*)d_in[9];

    float* tokens  = (float*)d_out;                 // [8192, 768]
    float* patches = (float*)d_out + TOK_ELEMS;     // [8192, 2304]

    // 1) conv + bias + BN + GELU + mask -> patches (fused)
    {
        dim3 grid(3, 12, NF*4);
        conv_bn_gelu_patch_kernel<<<grid, 256>>>(x, conv_w, conv_b,
                                                 gamma, beta, mean, var,
                                                 mask, patches);
    }
    // 2) projection GEMM + bias + GELU (reads masked patches from d_out)
    {
        dim3 grid(DIM/64, M_TOK/64);
        gemm_tokens_kernel<<<grid, 256>>>(patches, proj_w, proj_b, tokens);
    }
}

// round 3
// speedup vs baseline: 1.0555x; 1.0555x over previous
#include <cuda_runtime.h>
#include <math.h>
#include <stdint.h>

// ---------------- problem constants ----------------
#define NF      32          // B*S frames
#define C       64
#define H       96
#define W       96
#define FEAT    2304        // C*6*6
#define DIM     768
#define M_TOK   (NF*256)                    // 8192
#define TOK_ELEMS   (M_TOK*DIM)             // 6291456
#define FRAME_STRIDE (C*H*W)

// ---------------- packed f32x2 helpers ----------------
__device__ __forceinline__ unsigned long long pack2f(float lo, float hi){
    unsigned long long r;
    asm("mov.b64 %0, {%1, %2};" : "=l"(r)
        : "r"(__float_as_uint(lo)), "r"(__float_as_uint(hi)));
    return r;
}
__device__ __forceinline__ unsigned long long fma2(unsigned long long a,
                                                   unsigned long long b,
                                                   unsigned long long c){
    unsigned long long d;
    asm("fma.rn.f32x2 %0, %1, %2, %3;" : "=l"(d) : "l"(a), "l"(b), "l"(c));
    return d;
}
__device__ __forceinline__ float2 unpack2f(unsigned long long v){
    unsigned lo, hi;
    asm("mov.b64 {%0, %1}, %2;" : "=r"(lo), "=r"(hi) : "l"(v));
    return make_float2(__uint_as_float(lo), __uint_as_float(hi));
}
__device__ __forceinline__ uint32_t f2tf32(float x){
    uint32_t r;
    asm("cvt.rna.tf32.f32 %0, %1;" : "=r"(r) : "f"(x));
    return r;
}
__device__ __forceinline__ float gelu_exact(float x){
    return 0.5f*x*(1.0f + erff(x*0.7071067811865476f));
}

// =====================================================================
// Kernel 1: 3x3 conv (pad 1) + bias + BN + exact GELU + patch/mask
// 32 c_out per block (2x FMA per staged halo byte vs round 2).
// Block: 256 threads, tile 32(x) x 8(y). Thread: 8 c_out x 4 px (fma2).
// Double-buffered smem staging, 1 barrier per c_in.
// =====================================================================
__global__ __launch_bounds__(256, 2) void conv_bn_gelu_patch_kernel(
    const float* __restrict__ x,
    const float* __restrict__ cw,
    const float* __restrict__ cb,
    const float* __restrict__ gamma,
    const float* __restrict__ beta,
    const float* __restrict__ mean,
    const float* __restrict__ var,
    const float* __restrict__ mask,
    float* __restrict__ out_patches)
{
    __shared__ float s_in[2][10][36];                 // halo tile
    __shared__ unsigned long long s_w2[2][32][9];     // broadcast weight pairs {w,w}
    __shared__ float s_mask[36];

    const int tid = threadIdx.x;
    const int tc  = tid & 3;         // c_out sub-group (8 c_out each)
    const int tx  = (tid >> 2) & 7;  // x sub-tile (4 px)
    const int ty  = tid >> 5;        // y row (0..7)

    const int bx    = blockIdx.x;        // 0..2
    const int by    = blockIdx.y;        // 0..11
    const int frame = blockIdx.z >> 1;   // 0..31
    const int cog   = blockIdx.z & 1;    // c_out group of 32

    const float* xin = x + (long)frame * FRAME_STRIDE;
    const int y  = by*8 + ty;
    const int x0 = bx*32 + tx*4;

    // ---- prologue staging (ci = 0) ----
    if (tid < 36) s_mask[tid] = mask[tid];
    for (int i = tid; i < 340; i += 256){
        int r = i/34, cc = i%34;
        int gy = by*8 + r - 1, gx = bx*32 + cc - 1;
        float v = 0.f;
        if (gy>=0 && gy<H && gx>=0 && gx<W) v = xin[gy*W + gx];
        s_in[0][r][cc] = v;
    }
    for (int e = tid; e < 288; e += 256){
        int col = e/9, k = e%9;
        float w = cw[((cog*32+col)*C)*9 + k];
        s_w2[0][col][k] = pack2f(w, w);
    }
    __syncthreads();

    unsigned long long acc2[8][2];
    #pragma unroll
    for (int q=0;q<8;q++){ acc2[q][0]=0ULL; acc2[q][1]=0ULL; }

    for (int ci = 0; ci < C; ci++){
        const int cur = ci & 1;
        const bool hasnext = (ci + 1 < C);
        // ---- issue loads for next channel ----
        float vin0 = 0.f, vin1 = 0.f, wld0 = 0.f, wld1 = 0.f;
        if (hasnext){
            const float* xc = xin + (long)(ci+1)*H*W;
            { int r = tid/34, cc = tid%34;
              int gy = by*8 + r - 1, gx = bx*32 + cc - 1;
              if (gy>=0 && gy<H && gx>=0 && gx<W) vin0 = xc[gy*W + gx]; }
            if (tid + 256 < 340){
              int i1 = tid + 256;
              int r = i1/34, cc = i1%34;
              int gy = by*8 + r - 1, gx = bx*32 + cc - 1;
              if (gy>=0 && gy<H && gx>=0 && gx<W) vin1 = xc[gy*W + gx]; }
            { int col = tid/9, k = tid%9;
              wld0 = cw[((cog*32+col)*C + ci + 1)*9 + k]; }
            if (tid < 32){
              int e = tid + 256;
              int col = e/9, k = e%9;
              wld1 = cw[((cog*32+col)*C + ci + 1)*9 + k]; }
        }

        // ---- compute on current buffer ----
        unsigned long long p[3][5];
        #pragma unroll
        for (int dy=0; dy<3; dy++){
            const float* rp = &s_in[cur][ty+dy][tx*4];
            float4 v4 = *(const float4*)rp;
            float2 v2 = *(const float2*)(rp + 4);
            p[dy][0] = pack2f(v4.x, v4.y);
            p[dy][1] = pack2f(v4.y, v4.z);
            p[dy][2] = pack2f(v4.z, v4.w);
            p[dy][3] = pack2f(v4.w, v2.x);
            p[dy][4] = pack2f(v2.x, v2.y);
        }
        #pragma unroll
        for (int q=0;q<8;q++){
            const unsigned long long* wr = s_w2[cur][tc*8+q];
            #pragma unroll
            for (int ky=0;ky<3;ky++){
                #pragma unroll
                for (int kx=0;kx<3;kx++){
                    unsigned long long w = wr[ky*3+kx];
                    acc2[q][0] = fma2(p[ky][kx],   w, acc2[q][0]);
                    acc2[q][1] = fma2(p[ky][kx+2], w, acc2[q][1]);
                }
            }
        }

        // ---- commit staged data ----
        if (hasnext){
            const int nxt = cur ^ 1;
            { int r = tid/34, cc = tid%34; s_in[nxt][r][cc] = vin0; }
            if (tid + 256 < 340){
                int i1 = tid + 256;
                int r = i1/34, cc = i1%34; s_in[nxt][r][cc] = vin1; }
            { int col = tid/9, k = tid%9; s_w2[nxt][col][k] = pack2f(wld0, wld0); }
            if (tid < 32){
                int e = tid + 256;
                int col = e/9, k = e%9;
                s_w2[nxt][col][k] = pack2f(wld1, wld1); }
        }
        __syncthreads();
    }

    // ---- epilogue: bias + BN + GELU + mask -> patches layout ----
    const int l = y / 6, i_in = y - l*6;
    #pragma unroll
    for (int q=0;q<8;q++){
        const int co = cog*32 + tc*8 + q;
        const float s  = gamma[co] * rsqrtf(var[co] + 1e-5f);
        const float sh = beta[co] - mean[co]*s;
        const float b  = cb[co];
        float2 lo = unpack2f(acc2[q][0]);
        float2 hi = unpack2f(acc2[q][1]);
        float v[4] = {lo.x, lo.y, hi.x, hi.y};
        #pragma unroll
        for (int px=0;px<4;px++){
            const int xg = x0 + px;
            const int r  = xg / 6, j = xg - r*6;
            float o = gelu_exact((v[px] + b)*s + sh) * s_mask[i_in*6 + j];
            out_patches[((((long)frame*256 + l*16 + r)*64 + co)*36) + i_in*6 + j] = o;
        }
    }
}

// =====================================================================
// Kernel 2: tokens = gelu(A @ Wp^T + bias) via tf32 mma.sync.m16n8k8
// A = masked patches [8192, 2304], Wp [768, 2304], both K-major (NT).
// Block 128x64, BK=16, 8 warps, warp tile 32x32 (mt=2, nt=4).
// smem stride 20 -> conflict-free fragment loads. Double buffered.
// =====================================================================
#define GBM 128
#define GBN 64
#define GBK 16
#define SSTR 20

__device__ __forceinline__ void mma_tf32(float* d, const uint32_t* a, const uint32_t* b){
    asm volatile(
        "mma.sync.aligned.m16n8k8.row.col.f32.tf32.tf32.f32 "
        "{%0,%1,%2,%3}, {%4,%5,%6,%7}, {%8,%9}, {%0,%1,%2,%3};"
        : "+f"(d[0]), "+f"(d[1]), "+f"(d[2]), "+f"(d[3])
        : "r"(a[0]), "r"(a[1]), "r"(a[2]), "r"(a[3]), "r"(b[0]), "r"(b[1]));
}

__global__ __launch_bounds__(256, 2) void gemm_tokens_tf32_kernel(
    const float* __restrict__ A,
    const float* __restrict__ Wp,
    const float* __restrict__ bias,
    float* __restrict__ tok)
{
    __shared__ uint32_t s_a[2][GBM][SSTR];
    __shared__ uint32_t s_b[2][GBN][SSTR];

    const int tid  = threadIdx.x;
    const int lane = tid & 31;
    const int wid  = tid >> 5;
    const int wm   = wid & 3;     // warp m: 0..3 (32 rows each)
    const int wn   = wid >> 2;    // warp n: 0..1 (32 cols each)
    const int bm   = blockIdx.y;
    const int bn   = blockIdx.x;

    float acc[2][4][4];
    #pragma unroll
    for (int mt=0;mt<2;mt++)
        #pragma unroll
        for (int nt=0;nt<4;nt++)
            #pragma unroll
            for (int r=0;r<4;r++) acc[mt][nt][r] = 0.f;

    // staging indices: A = 512 float4 (2/thread), B = 128 float4 (tid<128)
    const int arow0 = tid >> 2;          // 0..63 (h adds 64)
    const int ac4   = (tid & 3) << 2;    // 0,4,8,12
    const bool hasB = (tid < 128);
    const int brow  = tid >> 2;          // 0..31 valid when hasB... (tid<128 -> 0..31)
    const int bc4   = (tid & 3) << 2;

    // ---- prologue: stage kt=0 into buf 0 ----
    {
        #pragma unroll
        for (int h=0; h<2; h++){
            int row = arow0 + h*64;
            float4 v = *(const float4*)(A + (long)(bm*GBM+row)*FEAT + ac4);
            s_a[0][row][ac4+0] = f2tf32(v.x); s_a[0][row][ac4+1] = f2tf32(v.y);
            s_a[0][row][ac4+2] = f2tf32(v.z); s_a[0][row][ac4+3] = f2tf32(v.w);
        }
        if (hasB){
            #pragma unroll
            for (int h=0; h<2; h++){
                int row = brow + h*32;
                float4 v = *(const float4*)(Wp + (long)(bn*GBN+row)*FEAT + bc4);
                s_b[0][row][bc4+0] = f2tf32(v.x); s_b[0][row][bc4+1] = f2tf32(v.y);
                s_b[0][row][bc4+2] = f2tf32(v.z); s_b[0][row][bc4+3] = f2tf32(v.w);
            }
        }
    }
    __syncthreads();

    const int NKT = FEAT / GBK;   // 144
    for (int kt = 0; kt < NKT; kt++){
        const int cur = kt & 1;
        const bool hasnext = (kt + 1 < NKT);
        float4 av[2], bv[2];
        if (hasnext){
            const int kg = (kt+1)*GBK;
            #pragma unroll
            for (int h=0; h<2; h++){
                int row = arow0 + h*64;
                av[h] = *(const float4*)(A + (long)(bm*GBM+row)*FEAT + kg + ac4);
            }
            if (hasB){
                #pragma unroll
                for (int h=0; h<2; h++){
                    int row = brow + h*32;
                    bv[h] = *(const float4*)(Wp + (long)(bn*GBN+row)*FEAT + kg + bc4);
                }
            }
        }

        // ---- compute: 2 k-slices of 8 ----
        #pragma unroll
        for (int ks=0; ks<2; ks++){
            const int kb = ks*8 + (lane & 3);
            uint32_t af[2][4], bf[4][2];
            #pragma unroll
            for (int mt=0;mt<2;mt++){
                int r0 = wm*32 + mt*16 + (lane >> 2);
                af[mt][0] = s_a[cur][r0  ][kb  ];
                af[mt][1] = s_a[cur][r0+8][kb  ];
                af[mt][2] = s_a[cur][r0  ][kb+4];
                af[mt][3] = s_a[cur][r0+8][kb+4];
            }
            #pragma unroll
            for (int nt=0;nt<4;nt++){
                int c0 = wn*32 + nt*8 + (lane >> 2);
                bf[nt][0] = s_b[cur][c0][kb  ];
                bf[nt][1] = s_b[cur][c0][kb+4];
            }
            #pragma unroll
            for (int mt=0;mt<2;mt++)
                #pragma unroll
                for (int nt=0;nt<4;nt++)
                    mma_tf32(acc[mt][nt], af[mt], bf[nt]);
        }

        // ---- commit next tile ----
        if (hasnext){
            const int nxt = cur ^ 1;
            #pragma unroll
            for (int h=0; h<2; h++){
                int row = arow0 + h*64;
                s_a[nxt][row][ac4+0] = f2tf32(av[h].x);
                s_a[nxt][row][ac4+1] = f2tf32(av[h].y);
                s_a[nxt][row][ac4+2] = f2tf32(av[h].z);
                s_a[nxt][row][ac4+3] = f2tf32(av[h].w);
            }
            if (hasB){
                #pragma unroll
                for (int h=0; h<2; h++){
                    int row = brow + h*32;
                    s_b[nxt][row][bc4+0] = f2tf32(bv[h].x);
                    s_b[nxt][row][bc4+1] = f2tf32(bv[h].y);
                    s_b[nxt][row][bc4+2] = f2tf32(bv[h].z);
                    s_b[nxt][row][bc4+3] = f2tf32(bv[h].w);
                }
            }
        }
        __syncthreads();
    }

    // ---- epilogue: bias + gelu ----
    #pragma unroll
    for (int mt=0;mt<2;mt++){
        const int r0 = bm*GBM + wm*32 + mt*16 + (lane >> 2);
        #pragma unroll
        for (int nt=0;nt<4;nt++){
            const int c0 = bn*GBN + wn*32 + nt*8 + ((lane & 3) << 1);
            float2 b2 = *(const float2*)(bias + c0);
            float2 o0, o1;
            o0.x = gelu_exact(acc[mt][nt][0] + b2.x);
            o0.y = gelu_exact(acc[mt][nt][1] + b2.y);
            o1.x = gelu_exact(acc[mt][nt][2] + b2.x);
            o1.y = gelu_exact(acc[mt][nt][3] + b2.y);
            *(float2*)(tok + (long)r0*DIM + c0)     = o0;
            *(float2*)(tok + (long)(r0+8)*DIM + c0) = o1;
        }
    }
}

// =====================================================================
extern "C" void kernel_launch(void* const* d_in, const int* in_sizes, int n_in,
                              void* d_out, int out_size)
{
    const float* x      = (const float*)d_in[0];
    const float* conv_w = (const float*)d_in[1];
    const float* conv_b = (const float*)d_in[2];
    const float* gamma  = (const float*)d_in[3];
    const float* beta   = (const float*)d_in[4];
    const float* mean   = (const float*)d_in[5];
    const float* var    = (const float*)d_in[6];
    const float* proj_w = (const float*)d_in[7];
    const float* proj_b = (const float*)d_in[8];
    const float* mask   = (const float*)d_in[9];

    float* tokens  = (float*)d_out;                 // [8192, 768]
    float* patches = (float*)d_out + TOK_ELEMS;     // [8192, 2304]

    // 1) conv + bias + BN + GELU + mask -> patches (fused)
    {
        dim3 grid(3, 12, NF*2);
        conv_bn_gelu_patch_kernel<<<grid, 256>>>(x, conv_w, conv_b,
                                                 gamma, beta, mean, var,
                                                 mask, patches);
    }
    // 2) projection GEMM + bias + GELU (tf32 tensor cores)
    {
        dim3 grid(DIM/GBN, M_TOK/GBM);
        gemm_tokens_tf32_kernel<<<grid, 256>>>(patches, proj_w, proj_b, tokens);
    }
}

// round 4
// speedup vs baseline: 2.3008x; 2.1798x over previous
#include <cuda_runtime.h>
#include <math.h>
#include <stdint.h>

// ---------------- problem constants ----------------
#define NF      32          // B*S frames
#define C       64
#define H       96
#define W       96
#define FEAT    2304        // C*6*6
#define DIM     768
#define M_TOK   (NF*256)                    // 8192
#define TOK_ELEMS   (M_TOK*DIM)             // 6291456
#define FRAME_STRIDE (C*H*W)

__device__ __forceinline__ uint32_t f2tf32(float x){
    uint32_t r;
    asm("cvt.rna.tf32.f32 %0, %1;" : "=r"(r) : "f"(x));
    return r;
}
__device__ __forceinline__ float gelu_exact(float x){
    return 0.5f*x*(1.0f + erff(x*0.7071067811865476f));
}
__device__ __forceinline__ void mma_tf32(float* d, const uint32_t* a, const uint32_t* b){
    asm volatile(
        "mma.sync.aligned.m16n8k8.row.col.f32.tf32.tf32.f32 "
        "{%0,%1,%2,%3}, {%4,%5,%6,%7}, {%8,%9}, {%0,%1,%2,%3};"
        : "+f"(d[0]), "+f"(d[1]), "+f"(d[2]), "+f"(d[3])
        : "r"(a[0]), "r"(a[1]), "r"(a[2]), "r"(a[3]), "r"(b[0]), "r"(b[1]));
}

// ---------------- prepped weights / BN constants (device globals) ----------------
__device__ float g_wh[9*64*64];     // [tap][ci][co], tf32-rounded hi part
__device__ float g_wl[9*64*64];     // residual lo part
__device__ float g_bnscale[64];
__device__ float g_bnshift[64];

// =====================================================================
// Kernel 0: weight repack [co][ci][tap] -> [tap][ci][co] with hi/lo
// split, plus fused BN scale/shift (conv bias folded in).
// =====================================================================
__global__ void prep_kernel(const float* __restrict__ cw,
                            const float* __restrict__ cb,
                            const float* __restrict__ gamma,
                            const float* __restrict__ beta,
                            const float* __restrict__ mean,
                            const float* __restrict__ var)
{
    int idx = blockIdx.x*256 + threadIdx.x;
    if (idx < 9*64*64){
        int co  = idx & 63;
        int ci  = (idx >> 6) & 63;
        int tap = idx >> 12;
        float v = cw[(co*64 + ci)*9 + tap];
        uint32_t hb = f2tf32(v);
        float hi = __uint_as_float(hb);
        g_wh[idx] = hi;
        g_wl[idx] = v - hi;
    }
    if (blockIdx.x == 0 && threadIdx.x < 64){
        int co = threadIdx.x;
        float s = gamma[co] * rsqrtf(var[co] + 1e-5f);
        g_bnscale[co] = s;
        g_bnshift[co] = (cb[co] - mean[co]) * s + beta[co];
    }
}

// =====================================================================
// Kernel 1: conv3x3 as implicit GEMM on tf32 tensor cores (3xTF32).
// Block: 128 spatial px (8 rows x 16 cols) x 64 c_out. 256 thr, 8 warps
// (4 m-warps x 2 n-warps), warp tile 32x32 (mt=2, nt=4).
// K loop: 4 ci-chunks of 16; inner: 9 taps (shifted A reads from halo).
// Epilogue: BN + exact GELU + mask, scatter into patches layout.
// =====================================================================
__global__ __launch_bounds__(256, 2) void conv_mma_kernel(
    const float* __restrict__ x,
    const float* __restrict__ mask,
    float* __restrict__ out_patches)
{
    __shared__ uint32_t s_xh[16][10][20];   // [ci][y][x], halo hi (ci stride 200 ≡ 8 mod 32)
    __shared__ uint32_t s_xl[16][10][20];   // halo lo
    __shared__ uint32_t s_bh[2][16][72];    // [buf][ci][co], ci stride 72 ≡ 8 mod 32
    __shared__ uint32_t s_bl[2][16][72];
    __shared__ float s_mask[36];
    __shared__ float s_scale[64], s_shift[64];

    const int tid  = threadIdx.x;
    const int lane = tid & 31;
    const int wid  = tid >> 5;
    const int wm   = wid & 3;          // m-warp (32 rows)
    const int wn   = wid >> 2;         // n-warp (32 cols)

    const int w0    = blockIdx.x * 16;
    const int h0    = blockIdx.y * 8;
    const int frame = blockIdx.z;
    const float* xf = x + (long)frame * FRAME_STRIDE;

    if (tid < 36) s_mask[tid] = mask[tid];
    if (tid < 64){ s_scale[tid] = g_bnscale[tid]; s_shift[tid] = g_bnshift[tid]; }

    float acc[2][4][4];
    #pragma unroll
    for (int mt=0;mt<2;mt++)
        #pragma unroll
        for (int nt=0;nt<4;nt++)
            #pragma unroll
            for (int r=0;r<4;r++) acc[mt][nt][r] = 0.f;

    for (int cg = 0; cg < 4; cg++){
        // ---- stage halo for this ci chunk (hi/lo split) ----
        for (int i = tid; i < 2880; i += 256){
            int ci_l = i / 180;
            int r2   = i - ci_l*180;
            int yy   = r2 / 18;
            int xx   = r2 - yy*18;
            int gy = h0 + yy - 1, gx = w0 + xx - 1;
            float v = 0.f;
            if (gy >= 0 && gy < H && gx >= 0 && gx < W)
                v = xf[(cg*16 + ci_l)*(H*W) + gy*W + gx];
            uint32_t hb = f2tf32(v);
            float hi = __uint_as_float(hb);
            s_xh[ci_l][yy][xx] = hb;
            s_xl[ci_l][yy][xx] = __float_as_uint(v - hi);
        }
        // ---- stage B for tap 0 into buf 0 ----
        #pragma unroll
        for (int j = 0; j < 4; j++){
            int i = tid + j*256;
            int ci_l = i >> 6, co = i & 63;
            int gidx = (0*64 + cg*16 + ci_l)*64 + co;
            s_bh[0][ci_l][co] = __float_as_uint(g_wh[gidx]);
            s_bl[0][ci_l][co] = __float_as_uint(g_wl[gidx]);
        }
        __syncthreads();

        for (int tap = 0; tap < 9; tap++){
            const int buf = tap & 1;
            const int ky = tap / 3, kx = tap - ky*3;

            // prefetch next tap's B into registers
            float nbh[4], nbl[4];
            if (tap < 8){
                #pragma unroll
                for (int j = 0; j < 4; j++){
                    int i = tid + j*256;
                    int ci_l = i >> 6, co = i & 63;
                    int gidx = ((tap+1)*64 + cg*16 + ci_l)*64 + co;
                    nbh[j] = g_wh[gidx];
                    nbl[j] = g_wl[gidx];
                }
            }

            // ---- mma: 2 k-slices of 8 ci each ----
            #pragma unroll
            for (int ks = 0; ks < 2; ks++){
                const int kb = ks*8 + (lane & 3);
                uint32_t afh[2][4], afl[2][4], bfh[4][2], bfl[4][2];
                #pragma unroll
                for (int mt = 0; mt < 2; mt++){
                    int r0 = wm*32 + mt*16 + (lane >> 2);
                    int py = (r0 >> 4) + ky;
                    int px = (r0 & 15) + kx;   // rows r0 and r0+8 share py; px and px+8
                    afh[mt][0] = s_xh[kb  ][py][px  ];
                    afh[mt][1] = s_xh[kb  ][py][px+8];
                    afh[mt][2] = s_xh[kb+4][py][px  ];
                    afh[mt][3] = s_xh[kb+4][py][px+8];
                    afl[mt][0] = s_xl[kb  ][py][px  ];
                    afl[mt][1] = s_xl[kb  ][py][px+8];
                    afl[mt][2] = s_xl[kb+4][py][px  ];
                    afl[mt][3] = s_xl[kb+4][py][px+8];
                }
                #pragma unroll
                for (int nt = 0; nt < 4; nt++){
                    int c0 = wn*32 + nt*8 + (lane >> 2);
                    bfh[nt][0] = s_bh[buf][kb  ][c0];
                    bfh[nt][1] = s_bh[buf][kb+4][c0];
                    bfl[nt][0] = s_bl[buf][kb  ][c0];
                    bfl[nt][1] = s_bl[buf][kb+4][c0];
                }
                #pragma unroll
                for (int mt = 0; mt < 2; mt++)
                    #pragma unroll
                    for (int nt = 0; nt < 4; nt++){
                        mma_tf32(acc[mt][nt], afh[mt], bfh[nt]);   // hi*hi
                        mma_tf32(acc[mt][nt], afh[mt], bfl[nt]);   // hi*lo
                        mma_tf32(acc[mt][nt], afl[mt], bfh[nt]);   // lo*hi
                    }
            }

            // commit prefetched B to the other buffer
            if (tap < 8){
                #pragma unroll
                for (int j = 0; j < 4; j++){
                    int i = tid + j*256;
                    int ci_l = i >> 6, co = i & 63;
                    s_bh[buf^1][ci_l][co] = __float_as_uint(nbh[j]);
                    s_bl[buf^1][ci_l][co] = __float_as_uint(nbl[j]);
                }
            }
            __syncthreads();
        }
    }

    // ---- epilogue: BN + GELU + mask -> patches [frame][patch][co][i][j] ----
    #pragma unroll
    for (int mt = 0; mt < 2; mt++){
        const int r0 = wm*32 + mt*16 + (lane >> 2);
        #pragma unroll
        for (int dr = 0; dr < 2; dr++){          // rows r0, r0+8
            const int r = r0 + dr*8;
            const int hh = h0 + (r >> 4);
            const int ww = w0 + (r & 15);
            const int l = hh / 6, i_in = hh - l*6;
            const int rr = ww / 6, j_in = ww - rr*6;
            const float mk = s_mask[i_in*6 + j_in];
            const long pbase = (((long)frame*256 + l*16 + rr)*64)*36 + i_in*6 + j_in;
            #pragma unroll
            for (int nt = 0; nt < 4; nt++){
                const int c0 = wn*32 + nt*8 + ((lane & 3) << 1);
                #pragma unroll
                for (int dc = 0; dc < 2; dc++){
                    const int co = c0 + dc;
                    const float v = acc[mt][nt][dr*2 + dc];
                    float o = gelu_exact(v*s_scale[co] + s_shift[co]) * mk;
                    out_patches[pbase + (long)co*36] = o;
                }
            }
        }
    }
}

// =====================================================================
// Kernel 2: tokens = gelu(A @ Wp^T + bias) via tf32 mma (round-3, known good)
// =====================================================================
#define GBM 128
#define GBN 64
#define GBK 16
#define SSTR 20

__global__ __launch_bounds__(256, 2) void gemm_tokens_tf32_kernel(
    const float* __restrict__ A,
    const float* __restrict__ Wp,
    const float* __restrict__ bias,
    float* __restrict__ tok)
{
    __shared__ uint32_t s_a[2][GBM][SSTR];
    __shared__ uint32_t s_b[2][GBN][SSTR];

    const int tid  = threadIdx.x;
    const int lane = tid & 31;
    const int wid  = tid >> 5;
    const int wm   = wid & 3;
    const int wn   = wid >> 2;
    const int bm   = blockIdx.y;
    const int bn   = blockIdx.x;

    float acc[2][4][4];
    #pragma unroll
    for (int mt=0;mt<2;mt++)
        #pragma unroll
        for (int nt=0;nt<4;nt++)
            #pragma unroll
            for (int r=0;r<4;r++) acc[mt][nt][r] = 0.f;

    const int arow0 = tid >> 2;
    const int ac4   = (tid & 3) << 2;
    const bool hasB = (tid < 128);
    const int brow  = tid >> 2;
    const int bc4   = (tid & 3) << 2;

    {
        #pragma unroll
        for (int h=0; h<2; h++){
            int row = arow0 + h*64;
            float4 v = *(const float4*)(A + (long)(bm*GBM+row)*FEAT + ac4);
            s_a[0][row][ac4+0] = f2tf32(v.x); s_a[0][row][ac4+1] = f2tf32(v.y);
            s_a[0][row][ac4+2] = f2tf32(v.z); s_a[0][row][ac4+3] = f2tf32(v.w);
        }
        if (hasB){
            #pragma unroll
            for (int h=0; h<2; h++){
                int row = brow + h*32;
                float4 v = *(const float4*)(Wp + (long)(bn*GBN+row)*FEAT + bc4);
                s_b[0][row][bc4+0] = f2tf32(v.x); s_b[0][row][bc4+1] = f2tf32(v.y);
                s_b[0][row][bc4+2] = f2tf32(v.z); s_b[0][row][bc4+3] = f2tf32(v.w);
            }
        }
    }
    __syncthreads();

    const int NKT = FEAT / GBK;   // 144
    for (int kt = 0; kt < NKT; kt++){
        const int cur = kt & 1;
        const bool hasnext = (kt + 1 < NKT);
        float4 av[2], bv[2];
        if (hasnext){
            const int kg = (kt+1)*GBK;
            #pragma unroll
            for (int h=0; h<2; h++){
                int row = arow0 + h*64;
                av[h] = *(const float4*)(A + (long)(bm*GBM+row)*FEAT + kg + ac4);
            }
            if (hasB){
                #pragma unroll
                for (int h=0; h<2; h++){
                    int row = brow + h*32;
                    bv[h] = *(const float4*)(Wp + (long)(bn*GBN+row)*FEAT + kg + bc4);
                }
            }
        }

        #pragma unroll
        for (int ks=0; ks<2; ks++){
            const int kb = ks*8 + (lane & 3);
            uint32_t af[2][4], bf[4][2];
            #pragma unroll
            for (int mt=0;mt<2;mt++){
                int r0 = wm*32 + mt*16 + (lane >> 2);
                af[mt][0] = s_a[cur][r0  ][kb  ];
                af[mt][1] = s_a[cur][r0+8][kb  ];
                af[mt][2] = s_a[cur][r0  ][kb+4];
                af[mt][3] = s_a[cur][r0+8][kb+4];
            }
            #pragma unroll
            for (int nt=0;nt<4;nt++){
                int c0 = wn*32 + nt*8 + (lane >> 2);
                bf[nt][0] = s_b[cur][c0][kb  ];
                bf[nt][1] = s_b[cur][c0][kb+4];
            }
            #pragma unroll
            for (int mt=0;mt<2;mt++)
                #pragma unroll
                for (int nt=0;nt<4;nt++)
                    mma_tf32(acc[mt][nt], af[mt], bf[nt]);
        }

        if (hasnext){
            const int nxt = cur ^ 1;
            #pragma unroll
            for (int h=0; h<2; h++){
                int row = arow0 + h*64;
                s_a[nxt][row][ac4+0] = f2tf32(av[h].x);
                s_a[nxt][row][ac4+1] = f2tf32(av[h].y);
                s_a[nxt][row][ac4+2] = f2tf32(av[h].z);
                s_a[nxt][row][ac4+3] = f2tf32(av[h].w);
            }
            if (hasB){
                #pragma unroll
                for (int h=0; h<2; h++){
                    int row = brow + h*32;
                    s_b[nxt][row][bc4+0] = f2tf32(bv[h].x);
                    s_b[nxt][row][bc4+1] = f2tf32(bv[h].y);
                    s_b[nxt][row][bc4+2] = f2tf32(bv[h].z);
                    s_b[nxt][row][bc4+3] = f2tf32(bv[h].w);
                }
            }
        }
        __syncthreads();
    }

    #pragma unroll
    for (int mt=0;mt<2;mt++){
        const int r0 = bm*GBM + wm*32 + mt*16 + (lane >> 2);
        #pragma unroll
        for (int nt=0;nt<4;nt++){
            const int c0 = bn*GBN + wn*32 + nt*8 + ((lane & 3) << 1);
            float2 b2 = *(const float2*)(bias + c0);
            float2 o0, o1;
            o0.x = gelu_exact(acc[mt][nt][0] + b2.x);
            o0.y = gelu_exact(acc[mt][nt][1] + b2.y);
            o1.x = gelu_exact(acc[mt][nt][2] + b2.x);
            o1.y = gelu_exact(acc[mt][nt][3] + b2.y);
            *(float2*)(tok + (long)r0*DIM + c0)     = o0;
            *(float2*)(tok + (long)(r0+8)*DIM + c0) = o1;
        }
    }
}

// =====================================================================
extern "C" void kernel_launch(void* const* d_in, const int* in_sizes, int n_in,
                              void* d_out, int out_size)
{
    const float* x      = (const float*)d_in[0];
    const float* conv_w = (const float*)d_in[1];
    const float* conv_b = (const float*)d_in[2];
    const float* gamma  = (const float*)d_in[3];
    const float* beta   = (const float*)d_in[4];
    const float* mean   = (const float*)d_in[5];
    const float* var    = (const float*)d_in[6];
    const float* proj_w = (const float*)d_in[7];
    const float* proj_b = (const float*)d_in[8];
    const float* mask   = (const float*)d_in[9];

    float* tokens  = (float*)d_out;                 // [8192, 768]
    float* patches = (float*)d_out + TOK_ELEMS;     // [8192, 2304]

    // 0) weight repack + BN fold
    prep_kernel<<<144, 256>>>(conv_w, conv_b, gamma, beta, mean, var);

    // 1) conv as implicit GEMM (3xTF32) + BN + GELU + mask -> patches
    {
        dim3 grid(W/16, H/8, NF);   // 6 x 12 x 32
        conv_mma_kernel<<<grid, 256>>>(x, mask, patches);
    }

    // 2) projection GEMM + bias + GELU (tf32 tensor cores)
    {
        dim3 grid(DIM/GBN, M_TOK/GBM);
        gemm_tokens_tf32_kernel<<<grid, 256>>>(patches, proj_w, proj_b, tokens);
    }
}

// round 5
// speedup vs baseline: 2.7101x; 1.1779x over previous
#include <cuda_runtime.h>
#include <math.h>
#include <stdint.h>

// ---------------- problem constants ----------------
#define NF      32          // B*S frames
#define C       64
#define H       96
#define W       96
#define FEAT    2304        // C*6*6
#define DIM     768
#define M_TOK   (NF*256)                    // 8192
#define TOK_ELEMS   (M_TOK*DIM)             // 6291456
#define FRAME_STRIDE (C*H*W)

__device__ __forceinline__ uint32_t f2tf32(float x){
    uint32_t r;
    asm("cvt.rna.tf32.f32 %0, %1;" : "=r"(r) : "f"(x));
    return r;
}
__device__ __forceinline__ float gelu_exact(float x){
    return 0.5f*x*(1.0f + erff(x*0.7071067811865476f));
}
__device__ __forceinline__ void mma_tf32(float* d, const uint32_t* a, const uint32_t* b){
    asm volatile(
        "mma.sync.aligned.m16n8k8.row.col.f32.tf32.tf32.f32 "
        "{%0,%1,%2,%3}, {%4,%5,%6,%7}, {%8,%9}, {%0,%1,%2,%3};"
        : "+f"(d[0]), "+f"(d[1]), "+f"(d[2]), "+f"(d[3])
        : "r"(a[0]), "r"(a[1]), "r"(a[2]), "r"(a[3]), "r"(b[0]), "r"(b[1]));
}
__device__ __forceinline__ void cp16(uint32_t saddr, const void* g){
    asm volatile("cp.async.cg.shared.global [%0], [%1], 16;" :: "r"(saddr), "l"(g));
}

// ---------------- device globals ----------------
__device__ float g_wh[9*64*64];        // conv weights [tap][ci][co], tf32 hi
__device__ float g_wl[9*64*64];        // conv weights residual lo
__device__ float g_bnscale[64];
__device__ float g_bnshift[64];
__device__ float g_w32[DIM*FEAT];      // proj_w pre-converted to tf32 bits
__device__ float g_a32[(long)M_TOK*FEAT]; // masked patches, tf32 bits

// =====================================================================
// Kernel 0: weight repack + BN fold + proj_w tf32 pre-convert
// =====================================================================
__global__ void prep_kernel(const float* __restrict__ cw,
                            const float* __restrict__ cb,
                            const float* __restrict__ gamma,
                            const float* __restrict__ beta,
                            const float* __restrict__ mean,
                            const float* __restrict__ var,
                            const float* __restrict__ pw)
{
    int idx = blockIdx.x*256 + threadIdx.x;
    if (idx < 9*64*64){
        int co  = idx & 63;
        int ci  = (idx >> 6) & 63;
        int tap = idx >> 12;
        float v = cw[(co*64 + ci)*9 + tap];
        float hi = __uint_as_float(f2tf32(v));
        g_wh[idx] = hi;
        g_wl[idx] = v - hi;
    }
    if (idx < DIM*FEAT)
        g_w32[idx] = __uint_as_float(f2tf32(pw[idx]));
    if (blockIdx.x == 0 && threadIdx.x < 64){
        int co = threadIdx.x;
        float s = gamma[co] * rsqrtf(var[co] + 1e-5f);
        g_bnscale[co] = s;
        g_bnshift[co] = (cb[co] - mean[co]) * s + beta[co];
    }
}

// =====================================================================
// Kernel 1: conv3x3 as implicit GEMM on tf32 tensor cores (3xTF32).
// Epilogue writes exact patches AND tf32 copy (GEMM A operand).
// =====================================================================
__global__ __launch_bounds__(256, 2) void conv_mma_kernel(
    const float* __restrict__ x,
    const float* __restrict__ mask,
    float* __restrict__ out_patches)
{
    __shared__ uint32_t s_xh[16][10][20];
    __shared__ uint32_t s_xl[16][10][20];
    __shared__ uint32_t s_bh[2][16][72];
    __shared__ uint32_t s_bl[2][16][72];
    __shared__ float s_mask[36];
    __shared__ float s_scale[64], s_shift[64];

    const int tid  = threadIdx.x;
    const int lane = tid & 31;
    const int wid  = tid >> 5;
    const int wm   = wid & 3;
    const int wn   = wid >> 2;

    const int w0    = blockIdx.x * 16;
    const int h0    = blockIdx.y * 8;
    const int frame = blockIdx.z;
    const float* xf = x + (long)frame * FRAME_STRIDE;

    if (tid < 36) s_mask[tid] = mask[tid];
    if (tid < 64){ s_scale[tid] = g_bnscale[tid]; s_shift[tid] = g_bnshift[tid]; }

    float acc[2][4][4];
    #pragma unroll
    for (int mt=0;mt<2;mt++)
        #pragma unroll
        for (int nt=0;nt<4;nt++)
            #pragma unroll
            for (int r=0;r<4;r++) acc[mt][nt][r] = 0.f;

    for (int cg = 0; cg < 4; cg++){
        for (int i = tid; i < 2880; i += 256){
            int ci_l = i / 180;
            int r2   = i - ci_l*180;
            int yy   = r2 / 18;
            int xx   = r2 - yy*18;
            int gy = h0 + yy - 1, gx = w0 + xx - 1;
            float v = 0.f;
            if (gy >= 0 && gy < H && gx >= 0 && gx < W)
                v = xf[(cg*16 + ci_l)*(H*W) + gy*W + gx];
            uint32_t hb = f2tf32(v);
            float hi = __uint_as_float(hb);
            s_xh[ci_l][yy][xx] = hb;
            s_xl[ci_l][yy][xx] = __float_as_uint(v - hi);
        }
        #pragma unroll
        for (int j = 0; j < 4; j++){
            int i = tid + j*256;
            int ci_l = i >> 6, co = i & 63;
            int gidx = (0*64 + cg*16 + ci_l)*64 + co;
            s_bh[0][ci_l][co] = __float_as_uint(g_wh[gidx]);
            s_bl[0][ci_l][co] = __float_as_uint(g_wl[gidx]);
        }
        __syncthreads();

        for (int tap = 0; tap < 9; tap++){
            const int buf = tap & 1;
            const int ky = tap / 3, kx = tap - ky*3;

            float nbh[4], nbl[4];
            if (tap < 8){
                #pragma unroll
                for (int j = 0; j < 4; j++){
                    int i = tid + j*256;
                    int ci_l = i >> 6, co = i & 63;
                    int gidx = ((tap+1)*64 + cg*16 + ci_l)*64 + co;
                    nbh[j] = g_wh[gidx];
                    nbl[j] = g_wl[gidx];
                }
            }

            #pragma unroll
            for (int ks = 0; ks < 2; ks++){
                const int kb = ks*8 + (lane & 3);
                uint32_t afh[2][4], afl[2][4], bfh[4][2], bfl[4][2];
                #pragma unroll
                for (int mt = 0; mt < 2; mt++){
                    int r0 = wm*32 + mt*16 + (lane >> 2);
                    int py = (r0 >> 4) + ky;
                    int px = (r0 & 15) + kx;
                    afh[mt][0] = s_xh[kb  ][py][px  ];
                    afh[mt][1] = s_xh[kb  ][py][px+8];
                    afh[mt][2] = s_xh[kb+4][py][px  ];
                    afh[mt][3] = s_xh[kb+4][py][px+8];
                    afl[mt][0] = s_xl[kb  ][py][px  ];
                    afl[mt][1] = s_xl[kb  ][py][px+8];
                    afl[mt][2] = s_xl[kb+4][py][px  ];
                    afl[mt][3] = s_xl[kb+4][py][px+8];
                }
                #pragma unroll
                for (int nt = 0; nt < 4; nt++){
                    int c0 = wn*32 + nt*8 + (lane >> 2);
                    bfh[nt][0] = s_bh[buf][kb  ][c0];
                    bfh[nt][1] = s_bh[buf][kb+4][c0];
                    bfl[nt][0] = s_bl[buf][kb  ][c0];
                    bfl[nt][1] = s_bl[buf][kb+4][c0];
                }
                #pragma unroll
                for (int mt = 0; mt < 2; mt++)
                    #pragma unroll
                    for (int nt = 0; nt < 4; nt++){
                        mma_tf32(acc[mt][nt], afh[mt], bfh[nt]);
                        mma_tf32(acc[mt][nt], afh[mt], bfl[nt]);
                        mma_tf32(acc[mt][nt], afl[mt], bfh[nt]);
                    }
            }

            if (tap < 8){
                #pragma unroll
                for (int j = 0; j < 4; j++){
                    int i = tid + j*256;
                    int ci_l = i >> 6, co = i & 63;
                    s_bh[buf^1][ci_l][co] = __float_as_uint(nbh[j]);
                    s_bl[buf^1][ci_l][co] = __float_as_uint(nbl[j]);
                }
            }
            __syncthreads();
        }
    }

    #pragma unroll
    for (int mt = 0; mt < 2; mt++){
        const int r0 = wm*32 + mt*16 + (lane >> 2);
        #pragma unroll
        for (int dr = 0; dr < 2; dr++){
            const int r = r0 + dr*8;
            const int hh = h0 + (r >> 4);
            const int ww = w0 + (r & 15);
            const int l = hh / 6, i_in = hh - l*6;
            const int rr = ww / 6, j_in = ww - rr*6;
            const float mk = s_mask[i_in*6 + j_in];
            const long pbase = (((long)frame*256 + l*16 + rr)*64)*36 + i_in*6 + j_in;
            #pragma unroll
            for (int nt = 0; nt < 4; nt++){
                const int c0 = wn*32 + nt*8 + ((lane & 3) << 1);
                #pragma unroll
                for (int dc = 0; dc < 2; dc++){
                    const int co = c0 + dc;
                    const float v = acc[mt][nt][dr*2 + dc];
                    float o = gelu_exact(v*s_scale[co] + s_shift[co]) * mk;
                    long oidx = pbase + (long)co*36;
                    out_patches[oidx] = o;
                    g_a32[oidx] = __uint_as_float(f2tf32(o));
                }
            }
        }
    }
}

// =====================================================================
// Kernel 2: tokens = gelu(A @ Wp^T + bias), tf32 mma + cp.async pipeline.
// Operands read from pre-converted device globals (no cvt, no LDG->STS).
// Block tile 128x64, GBK=32, 3-stage cp.async, stride-36 smem rows.
// =====================================================================
#define GBM 128
#define GBN 64
#define GBK 32
#define KSTR 36
#define STAGES 3
#define SA_WORDS (GBM*KSTR)
#define SB_WORDS (GBN*KSTR)
#define GEMM_SMEM_BYTES ((STAGES*(SA_WORDS+SB_WORDS))*4)   // 82944

__global__ __launch_bounds__(256, 2) void gemm_tokens_cp_kernel(
    const float* __restrict__ bias,
    float* __restrict__ tok)
{
    extern __shared__ uint32_t smdyn[];
    uint32_t* s_a = smdyn;
    uint32_t* s_b = smdyn + STAGES*SA_WORDS;
    const uint32_t sa_base = (uint32_t)__cvta_generic_to_shared(s_a);
    const uint32_t sb_base = (uint32_t)__cvta_generic_to_shared(s_b);

    const int tid  = threadIdx.x;
    const int lane = tid & 31;
    const int wid  = tid >> 5;
    const int wm   = wid & 3;
    const int wn   = wid >> 2;
    const int bm   = blockIdx.y;
    const int bn   = blockIdx.x;

    const float* Ab = g_a32 + (long)bm*GBM*FEAT;
    const float* Bb = g_w32 + (long)bn*GBN*FEAT;

    float acc[2][4][4];
    #pragma unroll
    for (int mt=0;mt<2;mt++)
        #pragma unroll
        for (int nt=0;nt<4;nt++)
            #pragma unroll
            for (int r=0;r<4;r++) acc[mt][nt][r] = 0.f;

    const int crowA = tid >> 3;          // base row for A chunks (j adds 32)
    const int ck4   = (tid & 7) << 2;

    // prologue: stages 0,1 in flight
    #pragma unroll
    for (int st = 0; st < 2; st++){
        const int kg = st*GBK;
        #pragma unroll
        for (int j = 0; j < 4; j++){
            int row = crowA + j*32;
            cp16(sa_base + (uint32_t)((st*GBM + row)*KSTR + ck4)*4,
                 Ab + (long)row*FEAT + kg + ck4);
        }
        #pragma unroll
        for (int j = 0; j < 2; j++){
            int row = crowA + j*32;
            if (row < GBN)
                cp16(sb_base + (uint32_t)((st*GBN + row)*KSTR + ck4)*4,
                     Bb + (long)row*FEAT + kg + ck4);
        }
        asm volatile("cp.async.commit_group;");
    }
    asm volatile("cp.async.wait_group 1;");
    __syncthreads();

    const int NKT = FEAT / GBK;   // 72
    for (int kt = 0; kt < NKT; kt++){
        const int cur = kt % STAGES;
        if (kt + 2 < NKT){
            const int st = (kt + 2) % STAGES;
            const int kg = (kt + 2)*GBK;
            #pragma unroll
            for (int j = 0; j < 4; j++){
                int row = crowA + j*32;
                cp16(sa_base + (uint32_t)((st*GBM + row)*KSTR + ck4)*4,
                     Ab + (long)row*FEAT + kg + ck4);
            }
            #pragma unroll
            for (int j = 0; j < 2; j++){
                int row = crowA + j*32;
                if (row < GBN)
                    cp16(sb_base + (uint32_t)((st*GBN + row)*KSTR + ck4)*4,
                         Bb + (long)row*FEAT + kg + ck4);
            }
        }
        asm volatile("cp.async.commit_group;");   // empty group in tail keeps count

        const uint32_t* pa = s_a + cur*SA_WORDS;
        const uint32_t* pb = s_b + cur*SB_WORDS;
        #pragma unroll
        for (int ks = 0; ks < 4; ks++){
            const int kb = ks*8 + (lane & 3);
            uint32_t af[2][4], bf[4][2];
            #pragma unroll
            for (int mt=0;mt<2;mt++){
                int r0 = wm*32 + mt*16 + (lane >> 2);
                af[mt][0] = pa[r0*KSTR + kb];
                af[mt][1] = pa[(r0+8)*KSTR + kb];
                af[mt][2] = pa[r0*KSTR + kb + 4];
                af[mt][3] = pa[(r0+8)*KSTR + kb + 4];
            }
            #pragma unroll
            for (int nt=0;nt<4;nt++){
                int c0 = wn*32 + nt*8 + (lane >> 2);
                bf[nt][0] = pb[c0*KSTR + kb];
                bf[nt][1] = pb[c0*KSTR + kb + 4];
            }
            #pragma unroll
            for (int mt=0;mt<2;mt++)
                #pragma unroll
                for (int nt=0;nt<4;nt++)
                    mma_tf32(acc[mt][nt], af[mt], bf[nt]);
        }

        asm volatile("cp.async.wait_group 1;");
        __syncthreads();
    }

    #pragma unroll
    for (int mt=0;mt<2;mt++){
        const int r0 = bm*GBM + wm*32 + mt*16 + (lane >> 2);
        #pragma unroll
        for (int nt=0;nt<4;nt++){
            const int c0 = bn*GBN + wn*32 + nt*8 + ((lane & 3) << 1);
            float2 b2 = *(const float2*)(bias + c0);
            float2 o0, o1;
            o0.x = gelu_exact(acc[mt][nt][0] + b2.x);
            o0.y = gelu_exact(acc[mt][nt][1] + b2.y);
            o1.x = gelu_exact(acc[mt][nt][2] + b2.x);
            o1.y = gelu_exact(acc[mt][nt][3] + b2.y);
            *(float2*)(tok + (long)r0*DIM + c0)     = o0;
            *(float2*)(tok + (long)(r0+8)*DIM + c0) = o1;
        }
    }
}

// =====================================================================
extern "C" void kernel_launch(void* const* d_in, const int* in_sizes, int n_in,
                              void* d_out, int out_size)
{
    const float* x      = (const float*)d_in[0];
    const float* conv_w = (const float*)d_in[1];
    const float* conv_b = (const float*)d_in[2];
    const float* gamma  = (const float*)d_in[3];
    const float* beta   = (const float*)d_in[4];
    const float* mean   = (const float*)d_in[5];
    const float* var    = (const float*)d_in[6];
    const float* proj_w = (const float*)d_in[7];
    const float* proj_b = (const float*)d_in[8];
    const float* mask   = (const float*)d_in[9];

    float* tokens  = (float*)d_out;                 // [8192, 768]
    float* patches = (float*)d_out + TOK_ELEMS;     // [8192, 2304]

    cudaFuncSetAttribute(gemm_tokens_cp_kernel,
                         cudaFuncAttributeMaxDynamicSharedMemorySize,
                         GEMM_SMEM_BYTES);

    // 0) weight repack + BN fold + proj_w tf32 convert
    prep_kernel<<<(DIM*FEAT + 255)/256, 256>>>(conv_w, conv_b, gamma, beta,
                                               mean, var, proj_w);

    // 1) conv as implicit GEMM (3xTF32) -> patches + tf32 A copy
    {
        dim3 grid(W/16, H/8, NF);
        conv_mma_kernel<<<grid, 256>>>(x, mask, patches);
    }

    // 2) projection GEMM + bias + GELU (cp.async pipelined tf32 mma)
    {
        dim3 grid(DIM/GBN, M_TOK/GBM);
        gemm_tokens_cp_kernel<<<grid, 256, GEMM_SMEM_BYTES>>>(proj_b, tokens);
    }
}

// round 6
// speedup vs baseline: 3.1942x; 1.1786x over previous
#include <cuda_runtime.h>
#include <cuda_bf16.h>
#include <math.h>
#include <stdint.h>

// ---------------- problem constants ----------------
#define NF      32          // B*S frames
#define C       64
#define H       96
#define W       96
#define FEAT    2304        // C*6*6
#define DIM     768
#define M_TOK   (NF*256)                    // 8192
#define TOK_ELEMS   (M_TOK*DIM)             // 6291456
#define FRAME_STRIDE (C*H*W)

__device__ __forceinline__ uint32_t f2tf32(float x){
    uint32_t r;
    asm("cvt.rna.tf32.f32 %0, %1;" : "=r"(r) : "f"(x));
    return r;
}
__device__ __forceinline__ float gelu_exact(float x){
    return 0.5f*x*(1.0f + erff(x*0.7071067811865476f));
}
__device__ __forceinline__ void mma_tf32(float* d, const uint32_t* a, const uint32_t* b){
    asm volatile(
        "mma.sync.aligned.m16n8k8.row.col.f32.tf32.tf32.f32 "
        "{%0,%1,%2,%3}, {%4,%5,%6,%7}, {%8,%9}, {%0,%1,%2,%3};"
        : "+f"(d[0]), "+f"(d[1]), "+f"(d[2]), "+f"(d[3])
        : "r"(a[0]), "r"(a[1]), "r"(a[2]), "r"(a[3]), "r"(b[0]), "r"(b[1]));
}
__device__ __forceinline__ void mma_bf16(float* d, const uint32_t* a, const uint32_t* b){
    asm volatile(
        "mma.sync.aligned.m16n8k16.row.col.f32.bf16.bf16.f32 "
        "{%0,%1,%2,%3}, {%4,%5,%6,%7}, {%8,%9}, {%0,%1,%2,%3};"
        : "+f"(d[0]), "+f"(d[1]), "+f"(d[2]), "+f"(d[3])
        : "r"(a[0]), "r"(a[1]), "r"(a[2]), "r"(a[3]), "r"(b[0]), "r"(b[1]));
}
__device__ __forceinline__ void cp16(uint32_t saddr, const void* g){
    asm volatile("cp.async.cg.shared.global [%0], [%1], 16;" :: "r"(saddr), "l"(g));
}
// pack two bf16 (a -> low half) into u32
__device__ __forceinline__ uint32_t packbf2(__nv_bfloat16 a, __nv_bfloat16 b){
    uint32_t lo = (uint32_t)__bfloat16_as_ushort(a);
    uint32_t hi = (uint32_t)__bfloat16_as_ushort(b);
    return (hi << 16) | lo;
}
// split v into bf16 hi + bf16 lo residual
__device__ __forceinline__ void bf16split(float v, __nv_bfloat16& h, __nv_bfloat16& l){
    h = __float2bfloat16_rn(v);
    l = __float2bfloat16_rn(v - __bfloat162float(h));
}

// ---------------- device globals ----------------
__device__ uint32_t g_wbh[9*4*8*64];   // conv weights [tap][cg][ci-pair][co], bf16x2 hi
__device__ uint32_t g_wbl[9*4*8*64];   // bf16x2 lo residual
__device__ float g_bnscale[64];
__device__ float g_bnshift[64];
__device__ float g_w32[DIM*FEAT];      // proj_w pre-converted to tf32 bits
__device__ float g_a32[(long)M_TOK*FEAT]; // masked patches, tf32 bits

// =====================================================================
// Kernel 0: conv-weight bf16-split repack + BN fold + proj_w tf32 convert
// =====================================================================
__global__ void prep_kernel(const float* __restrict__ cw,
                            const float* __restrict__ cb,
                            const float* __restrict__ gamma,
                            const float* __restrict__ beta,
                            const float* __restrict__ mean,
                            const float* __restrict__ var,
                            const float* __restrict__ pw)
{
    int idx = blockIdx.x*256 + threadIdx.x;
    if (idx < 9*4*8*64){
        int co  = idx & 63;
        int c   = (idx >> 6) & 7;
        int cg  = (idx >> 9) & 3;
        int tap = idx >> 11;
        int ci0 = cg*16 + 2*c;
        float w0 = cw[(co*64 + ci0)*9 + tap];
        float w1 = cw[(co*64 + ci0 + 1)*9 + tap];
        __nv_bfloat16 h0, l0, h1, l1;
        bf16split(w0, h0, l0);
        bf16split(w1, h1, l1);
        g_wbh[idx] = packbf2(h0, h1);
        g_wbl[idx] = packbf2(l0, l1);
    }
    if (idx < DIM*FEAT)
        g_w32[idx] = __uint_as_float(f2tf32(pw[idx]));
    if (blockIdx.x == 0 && threadIdx.x < 64){
        int co = threadIdx.x;
        float s = gamma[co] * rsqrtf(var[co] + 1e-5f);
        g_bnscale[co] = s;
        g_bnshift[co] = (cb[co] - mean[co]) * s + beta[co];
    }
}

// =====================================================================
// Kernel 1: conv3x3 as implicit GEMM, 3xBF16 (m16n8k16) tensor cores.
// Block: 128 spatial px (8x16) x 64 c_out, 256 thr, 8 warps (4m x 2n),
// warp tile 32x32. K loop: 4 ci-chunks of 16 (= exactly one mma-K) x 9 taps.
// Epilogue: BN + exact GELU + mask -> patches (fp32) + tf32 copy for GEMM.
// =====================================================================
__global__ __launch_bounds__(256, 2) void conv_mma_kernel(
    const float* __restrict__ x,
    const float* __restrict__ mask,
    float* __restrict__ out_patches)
{
    __shared__ uint32_t s_xh[8][10][20];    // [ci-pair][y][x], bf16x2 hi
    __shared__ uint32_t s_xl[8][10][20];    // lo residual
    __shared__ uint32_t s_bh[2][8][72];     // [buf][ci-pair][co] (pad 72 = 8 mod 32)
    __shared__ uint32_t s_bl[2][8][72];
    __shared__ float s_mask[36];
    __shared__ float s_scale[64], s_shift[64];

    const int tid  = threadIdx.x;
    const int lane = tid & 31;
    const int wid  = tid >> 5;
    const int wm   = wid & 3;
    const int wn   = wid >> 2;
    const int lg   = lane >> 2;      // group id 0..7
    const int lt   = lane & 3;       // thread-in-group 0..3 (= ci-pair idx)

    const int w0    = blockIdx.x * 16;
    const int h0    = blockIdx.y * 8;
    const int frame = blockIdx.z;
    const float* xf = x + (long)frame * FRAME_STRIDE;

    if (tid < 36) s_mask[tid] = mask[tid];
    if (tid < 64){ s_scale[tid] = g_bnscale[tid]; s_shift[tid] = g_bnshift[tid]; }

    float acc[2][4][4];
    #pragma unroll
    for (int mt=0;mt<2;mt++)
        #pragma unroll
        for (int nt=0;nt<4;nt++)
            #pragma unroll
            for (int r=0;r<4;r++) acc[mt][nt][r] = 0.f;

    for (int cg = 0; cg < 4; cg++){
        // ---- stage halo for this ci chunk: 8 pairs x 10y x 20x ----
        for (int i = tid; i < 1600; i += 256){
            int c  = i / 200;
            int r2 = i - c*200;
            int yy = r2 / 20;
            int xx = r2 - yy*20;
            int gy = h0 + yy - 1, gx = w0 + xx - 1;
            float v0 = 0.f, v1 = 0.f;
            if (gy >= 0 && gy < H && gx >= 0 && gx < W){
                long base = (long)(cg*16 + 2*c)*(H*W) + gy*W + gx;
                v0 = xf[base];
                v1 = xf[base + H*W];
            }
            __nv_bfloat16 h0b, l0b, h1b, l1b;
            bf16split(v0, h0b, l0b);
            bf16split(v1, h1b, l1b);
            s_xh[c][yy][xx] = packbf2(h0b, h1b);
            s_xl[c][yy][xx] = packbf2(l0b, l1b);
        }
        // ---- stage B for tap 0 into buf 0 (512 u32 each) ----
        #pragma unroll
        for (int j = 0; j < 2; j++){
            int i = tid + j*256;
            int c = i >> 6, co = i & 63;
            int gidx = ((0*4 + cg)*8 + c)*64 + co;
            s_bh[0][c][co] = g_wbh[gidx];
            s_bl[0][c][co] = g_wbl[gidx];
        }
        __syncthreads();

        for (int tap = 0; tap < 9; tap++){
            const int buf = tap & 1;
            const int ky = tap / 3, kx = tap - ky*3;

            // prefetch next tap's B into registers
            uint32_t nbh[2], nbl[2];
            if (tap < 8){
                #pragma unroll
                for (int j = 0; j < 2; j++){
                    int i = tid + j*256;
                    int c = i >> 6, co = i & 63;
                    int gidx = (((tap+1)*4 + cg)*8 + c)*64 + co;
                    nbh[j] = g_wbh[gidx];
                    nbl[j] = g_wbl[gidx];
                }
            }

            // ---- fragments ----
            uint32_t ah[2][4], al[2][4], bh[4][2], bl[4][2];
            #pragma unroll
            for (int mt = 0; mt < 2; mt++){
                int r0 = wm*32 + mt*16 + lg;
                int py = (r0 >> 4) + ky;
                int px = (r0 & 15) + kx;
                ah[mt][0] = s_xh[lt  ][py][px  ];
                ah[mt][1] = s_xh[lt  ][py][px+8];
                ah[mt][2] = s_xh[lt+4][py][px  ];
                ah[mt][3] = s_xh[lt+4][py][px+8];
                al[mt][0] = s_xl[lt  ][py][px  ];
                al[mt][1] = s_xl[lt  ][py][px+8];
                al[mt][2] = s_xl[lt+4][py][px  ];
                al[mt][3] = s_xl[lt+4][py][px+8];
            }
            #pragma unroll
            for (int nt = 0; nt < 4; nt++){
                int co = wn*32 + nt*8 + lg;
                bh[nt][0] = s_bh[buf][lt  ][co];
                bh[nt][1] = s_bh[buf][lt+4][co];
                bl[nt][0] = s_bl[buf][lt  ][co];
                bl[nt][1] = s_bl[buf][lt+4][co];
            }
            #pragma unroll
            for (int mt = 0; mt < 2; mt++)
                #pragma unroll
                for (int nt = 0; nt < 4; nt++){
                    mma_bf16(acc[mt][nt], ah[mt], bh[nt]);   // hi*hi
                    mma_bf16(acc[mt][nt], ah[mt], bl[nt]);   // hi*lo
                    mma_bf16(acc[mt][nt], al[mt], bh[nt]);   // lo*hi
                }

            // commit prefetched B
            if (tap < 8){
                #pragma unroll
                for (int j = 0; j < 2; j++){
                    int i = tid + j*256;
                    int c = i >> 6, co = i & 63;
                    s_bh[buf^1][c][co] = nbh[j];
                    s_bl[buf^1][c][co] = nbl[j];
                }
            }
            __syncthreads();
        }
    }

    // ---- epilogue: BN + GELU + mask -> patches + tf32 copy ----
    #pragma unroll
    for (int mt = 0; mt < 2; mt++){
        const int r0 = wm*32 + mt*16 + lg;
        #pragma unroll
        for (int dr = 0; dr < 2; dr++){
            const int r = r0 + dr*8;
            const int hh = h0 + (r >> 4);
            const int ww = w0 + (r & 15);
            const int l = hh / 6, i_in = hh - l*6;
            const int rr = ww / 6, j_in = ww - rr*6;
            const float mk = s_mask[i_in*6 + j_in];
            const long pbase = (((long)frame*256 + l*16 + rr)*64)*36 + i_in*6 + j_in;
            #pragma unroll
            for (int nt = 0; nt < 4; nt++){
                const int c0 = wn*32 + nt*8 + (lt << 1);
                #pragma unroll
                for (int dc = 0; dc < 2; dc++){
                    const int co = c0 + dc;
                    const float v = acc[mt][nt][dr*2 + dc];
                    float o = gelu_exact(v*s_scale[co] + s_shift[co]) * mk;
                    long oidx = pbase + (long)co*36;
                    out_patches[oidx] = o;
                    g_a32[oidx] = __uint_as_float(f2tf32(o));
                }
            }
        }
    }
}

// =====================================================================
// Kernel 2: tokens = gelu(A @ Wp^T + bias), tf32 mma + cp.async pipeline
// (round-5 kernel, known good)
// =====================================================================
#define GBM 128
#define GBN 64
#define GBK 32
#define KSTR 36
#define STAGES 3
#define SA_WORDS (GBM*KSTR)
#define SB_WORDS (GBN*KSTR)
#define GEMM_SMEM_BYTES ((STAGES*(SA_WORDS+SB_WORDS))*4)   // 82944

__global__ __launch_bounds__(256, 2) void gemm_tokens_cp_kernel(
    const float* __restrict__ bias,
    float* __restrict__ tok)
{
    extern __shared__ uint32_t smdyn[];
    uint32_t* s_a = smdyn;
    uint32_t* s_b = smdyn + STAGES*SA_WORDS;
    const uint32_t sa_base = (uint32_t)__cvta_generic_to_shared(s_a);
    const uint32_t sb_base = (uint32_t)__cvta_generic_to_shared(s_b);

    const int tid  = threadIdx.x;
    const int lane = tid & 31;
    const int wid  = tid >> 5;
    const int wm   = wid & 3;
    const int wn   = wid >> 2;
    const int bm   = blockIdx.y;
    const int bn   = blockIdx.x;

    const float* Ab = g_a32 + (long)bm*GBM*FEAT;
    const float* Bb = g_w32 + (long)bn*GBN*FEAT;

    float acc[2][4][4];
    #pragma unroll
    for (int mt=0;mt<2;mt++)
        #pragma unroll
        for (int nt=0;nt<4;nt++)
            #pragma unroll
            for (int r=0;r<4;r++) acc[mt][nt][r] = 0.f;

    const int crowA = tid >> 3;
    const int ck4   = (tid & 7) << 2;

    #pragma unroll
    for (int st = 0; st < 2; st++){
        const int kg = st*GBK;
        #pragma unroll
        for (int j = 0; j < 4; j++){
            int row = crowA + j*32;
            cp16(sa_base + (uint32_t)((st*GBM + row)*KSTR + ck4)*4,
                 Ab + (long)row*FEAT + kg + ck4);
        }
        #pragma unroll
        for (int j = 0; j < 2; j++){
            int row = crowA + j*32;
            if (row < GBN)
                cp16(sb_base + (uint32_t)((st*GBN + row)*KSTR + ck4)*4,
                     Bb + (long)row*FEAT + kg + ck4);
        }
        asm volatile("cp.async.commit_group;");
    }
    asm volatile("cp.async.wait_group 1;");
    __syncthreads();

    const int NKT = FEAT / GBK;   // 72
    for (int kt = 0; kt < NKT; kt++){
        const int cur = kt % STAGES;
        if (kt + 2 < NKT){
            const int st = (kt + 2) % STAGES;
            const int kg = (kt + 2)*GBK;
            #pragma unroll
            for (int j = 0; j < 4; j++){
                int row = crowA + j*32;
                cp16(sa_base + (uint32_t)((st*GBM + row)*KSTR + ck4)*4,
                     Ab + (long)row*FEAT + kg + ck4);
            }
            #pragma unroll
            for (int j = 0; j < 2; j++){
                int row = crowA + j*32;
                if (row < GBN)
                    cp16(sb_base + (uint32_t)((st*GBN + row)*KSTR + ck4)*4,
                         Bb + (long)row*FEAT + kg + ck4);
            }
        }
        asm volatile("cp.async.commit_group;");

        const uint32_t* pa = s_a + cur*SA_WORDS;
        const uint32_t* pb = s_b + cur*SB_WORDS;
        #pragma unroll
        for (int ks = 0; ks < 4; ks++){
            const int kb = ks*8 + (lane & 3);
            uint32_t af[2][4], bf[4][2];
            #pragma unroll
            for (int mt=0;mt<2;mt++){
                int r0 = wm*32 + mt*16 + (lane >> 2);
                af[mt][0] = pa[r0*KSTR + kb];
                af[mt][1] = pa[(r0+8)*KSTR + kb];
                af[mt][2] = pa[r0*KSTR + kb + 4];
                af[mt][3] = pa[(r0+8)*KSTR + kb + 4];
            }
            #pragma unroll
            for (int nt=0;nt<4;nt++){
                int c0 = wn*32 + nt*8 + (lane >> 2);
                bf[nt][0] = pb[c0*KSTR + kb];
                bf[nt][1] = pb[c0*KSTR + kb + 4];
            }
            #pragma unroll
            for (int mt=0;mt<2;mt++)
                #pragma unroll
                for (int nt=0;nt<4;nt++)
                    mma_tf32(acc[mt][nt], af[mt], bf[nt]);
        }

        asm volatile("cp.async.wait_group 1;");
        __syncthreads();
    }

    #pragma unroll
    for (int mt=0;mt<2;mt++){
        const int r0 = bm*GBM + wm*32 + mt*16 + (lane >> 2);
        #pragma unroll
        for (int nt=0;nt<4;nt++){
            const int c0 = bn*GBN + wn*32 + nt*8 + ((lane & 3) << 1);
            float2 b2 = *(const float2*)(bias + c0);
            float2 o0, o1;
            o0.x = gelu_exact(acc[mt][nt][0] + b2.x);
            o0.y = gelu_exact(acc[mt][nt][1] + b2.y);
            o1.x = gelu_exact(acc[mt][nt][2] + b2.x);
            o1.y = gelu_exact(acc[mt][nt][3] + b2.y);
            *(float2*)(tok + (long)r0*DIM + c0)     = o0;
            *(float2*)(tok + (long)(r0+8)*DIM + c0) = o1;
        }
    }
}

// =====================================================================
extern "C" void kernel_launch(void* const* d_in, const int* in_sizes, int n_in,
                              void* d_out, int out_size)
{
    const float* x      = (const float*)d_in[0];
    const float* conv_w = (const float*)d_in[1];
    const float* conv_b = (const float*)d_in[2];
    const float* gamma  = (const float*)d_in[3];
    const float* beta   = (const float*)d_in[4];
    const float* mean   = (const float*)d_in[5];
    const float* var    = (const float*)d_in[6];
    const float* proj_w = (const float*)d_in[7];
    const float* proj_b = (const float*)d_in[8];
    const float* mask   = (const float*)d_in[9];

    float* tokens  = (float*)d_out;                 // [8192, 768]
    float* patches = (float*)d_out + TOK_ELEMS;     // [8192, 2304]

    cudaFuncSetAttribute(gemm_tokens_cp_kernel,
                         cudaFuncAttributeMaxDynamicSharedMemorySize,
                         GEMM_SMEM_BYTES);

    // 0) weight repack (bf16 split) + BN fold + proj_w tf32 convert
    prep_kernel<<<(DIM*FEAT + 255)/256, 256>>>(conv_w, conv_b, gamma, beta,
                                               mean, var, proj_w);

    // 1) conv as implicit GEMM (3xBF16) -> patches + tf32 A copy
    {
        dim3 grid(W/16, H/8, NF);
        conv_mma_kernel<<<grid, 256>>>(x, mask, patches);
    }

    // 2) projection GEMM + bias + GELU (cp.async pipelined tf32 mma)
    {
        dim3 grid(DIM/GBN, M_TOK/GBM);
        gemm_tokens_cp_kernel<<<grid, 256, GEMM_SMEM_BYTES>>>(proj_b, tokens);
    }
}